// round 9
// baseline (speedup 1.0000x reference)
#include <cuda_runtime.h>
#include <cuda_bf16.h>

#define BB     4
#define NN     8192
#define CC     256
#define POOLN  2048
#define NBR    4
#define TILE_PTS   2048                  // smem tile: first 2048 points of the batch
#define TILE_FLOATS (TILE_PTS * 3)       // 24 KB
#define QPB    8                         // queries (warps) per block
#define HARD_GRID 1024
#define SEG    (NN / 8)                  // 1024 points per warp segment

__device__ int g_hard_list[BB * POOLN];
__device__ int g_hard_count;             // zero-initialized; self-resetting
__device__ int g_hard_done;              // zero-initialized; self-resetting

__device__ __forceinline__ float decode_radius(const int* radius_raw)
{
    const unsigned rv = (unsigned)__ldg(radius_raw);
    return (rv & 0x7F800000u) ? __int_as_float((int)rv) : (float)(int)rv;
}

// ---------------- Easy pass: 8 queries per block, smem vertex tile ----------------
__global__ __launch_bounds__(256)
void pool_easy_kernel(const float* __restrict__ verts,
                      const float* __restrict__ feat,
                      const int*   __restrict__ radius_raw,
                      const int*   __restrict__ sample_idx,
                      float* __restrict__ outV,
                      float* __restrict__ outF)
{
    __shared__ float s_tile[TILE_FLOATS];   // raw (x,y,z)*2048 of this batch

    const int wid  = threadIdx.x >> 5;
    const int lane = threadIdx.x & 31;
    const int qid  = blockIdx.x * QPB + wid;         // 0 .. BB*POOLN-1
    const int b    = qid >> 11;                      // / POOLN (uniform per block)
    const int s    = qid & (POOLN - 1);

    // Cooperative tile load: 1536 float4 slots, coalesced.
    {
        const float4* __restrict__ src =
            (const float4*)(verts + (size_t)b * NN * 3);
        float4* dst = (float4*)s_tile;
        #pragma unroll
        for (int i = 0; i < TILE_FLOATS / 4 / 256; i++)
            dst[threadIdx.x + 256 * i] = src[threadIdx.x + 256 * i];
    }

    const int n = sample_idx[s];
    const float* vb = verts + (size_t)b * NN * 3;
    const float qx = vb[n * 3 + 0];
    const float qy = vb[n * 3 + 1];
    const float qz = vb[n * 3 + 2];
    const float sqn = qx * qx + qy * qy + qz * qz;

    const float radius = decode_radius(radius_raw);
    const float r2 = radius * radius;

    // vertices_pool (always written here)
    if (lane < 3) {
        const float v = (lane == 0) ? qx : (lane == 1) ? qy : qz;
        outV[((size_t)b * POOLN + s) * 3 + lane] = v;
    }

    __syncthreads();

    // ---- scan smem tile, first NBR ascending qualifiers ----
    int idx[NBR];
    int cnt = 0;
    #pragma unroll
    for (int k = 0; k < NBR; k++) idx[k] = n;

    for (int base = 0; base < TILE_PTS; base += 128) {
        unsigned bal[4];
        #pragma unroll
        for (int t = 0; t < 4; t++) {
            const int p = base + t * 32 + lane;
            const float px = s_tile[3 * p + 0];
            const float py = s_tile[3 * p + 1];
            const float pz = s_tile[3 * p + 2];
            const float d = -2.0f * (px * qx + py * qy + pz * qz) + sqn
                            + (px * px + py * py + pz * pz);
            bal[t] = __ballot_sync(0xFFFFFFFFu, !(d > r2));
        }
        #pragma unroll
        for (int t = 0; t < 4; t++) {
            unsigned m = bal[t];
            while (m && cnt < NBR) {
                idx[cnt++] = base + t * 32 + (__ffs(m) - 1);
                m &= m - 1;
            }
        }
        if (cnt >= NBR) break;   // uniform (ballot-derived)
    }

    if (cnt < NBR) {             // rare: defer to hard pass
        if (lane == 0) {
            const int pos = atomicAdd(&g_hard_count, 1);
            g_hard_list[pos] = qid;
        }
        return;
    }

    // ---- gather 4 feature rows (float4), max, store ----
    const float* fb = feat + (size_t)b * NN * CC;
    const float4* __restrict__ f0 = (const float4*)(fb + (size_t)idx[0] * CC);
    const float4* __restrict__ f1 = (const float4*)(fb + (size_t)idx[1] * CC);
    const float4* __restrict__ f2 = (const float4*)(fb + (size_t)idx[2] * CC);
    const float4* __restrict__ f3 = (const float4*)(fb + (size_t)idx[3] * CC);
    float4* __restrict__ fo = (float4*)(outF + ((size_t)b * POOLN + s) * CC);

    #pragma unroll
    for (int j = 0; j < CC / 128; j++) {
        const int c = lane + j * 32;
        float4 a = f0[c];
        const float4 v1 = f1[c], v2 = f2[c], v3 = f3[c];
        a.x = fmaxf(fmaxf(a.x, v1.x), fmaxf(v2.x, v3.x));
        a.y = fmaxf(fmaxf(a.y, v1.y), fmaxf(v2.y, v3.y));
        a.z = fmaxf(fmaxf(a.z, v1.z), fmaxf(v2.z, v3.z));
        a.w = fmaxf(fmaxf(a.w, v1.w), fmaxf(v2.w, v3.w));
        fo[c] = a;
    }
}

// ---------------- Hard pass: block per query; 8 coalesced warp segments ----------------
// Each warp scans its ascending 1024-point segment with lane-per-point loads
// (nL~4 per warp-load instead of 32 -> no L1tex wavefront blowup), early-exits
// at 4 segment qualifiers. Thread 0 merges per-warp lists in segment order.
__global__ __launch_bounds__(256, 4)
void pool_hard_kernel(const float* __restrict__ verts,
                      const float* __restrict__ feat,
                      const int*   __restrict__ radius_raw,
                      const int*   __restrict__ sample_idx,
                      float* __restrict__ outF)
{
    const int nhard = g_hard_count;
    const float radius = decode_radius(radius_raw);
    const float r2 = radius * radius;

    const int wid  = threadIdx.x >> 5;
    const int lane = threadIdx.x & 31;

    __shared__ int s_cnt[8];
    __shared__ int s_list[8][NBR];
    __shared__ int s_idx[NBR];

    for (int it = blockIdx.x; it < nhard; it += gridDim.x) {
        const int qid = g_hard_list[it];
        const int b = qid >> 11;
        const int s = qid & (POOLN - 1);

        const int n = sample_idx[s];
        const float* vb = verts + (size_t)b * NN * 3;
        const float qx = vb[n * 3 + 0];
        const float qy = vb[n * 3 + 1];
        const float qz = vb[n * 3 + 2];
        const float sqn = qx * qx + qy * qy + qz * qz;

        // ---- warp scans its segment [wid*SEG, (wid+1)*SEG) ----
        int idx[NBR];
        int cnt = 0;
        const int seg = wid * SEG;

        for (int base = 0; base < SEG; base += 128) {
            unsigned bal[4];
            #pragma unroll
            for (int t = 0; t < 4; t++) {
                const int p = seg + base + t * 32 + lane;
                const float px = vb[3 * p + 0];
                const float py = vb[3 * p + 1];
                const float pz = vb[3 * p + 2];
                const float d = -2.0f * (px * qx + py * qy + pz * qz) + sqn
                                + (px * px + py * py + pz * pz);
                bal[t] = __ballot_sync(0xFFFFFFFFu, !(d > r2));
            }
            #pragma unroll
            for (int t = 0; t < 4; t++) {
                unsigned m = bal[t];
                while (m && cnt < NBR) {
                    idx[cnt++] = seg + base + t * 32 + (__ffs(m) - 1);
                    m &= m - 1;
                }
            }
            if (cnt >= NBR) break;   // uniform within warp
        }

        if (lane == 0) {
            s_cnt[wid] = cnt;
            #pragma unroll
            for (int k = 0; k < NBR; k++) s_list[wid][k] = (k < cnt) ? idx[k] : 0;
        }
        __syncthreads();

        // ---- merge: segments are ascending, lists internally ascending ----
        if (threadIdx.x == 0) {
            int tot = 0;
            #pragma unroll
            for (int w = 0; w < 8; w++) {
                const int cw = s_cnt[w];
                for (int k = 0; k < cw && tot < NBR; k++)
                    s_idx[tot++] = s_list[w][k];
                if (tot >= NBR) break;
            }
            // tot >= 1 always (self point qualifies in its own segment)
            for (int k = tot; k < NBR; k++) s_idx[k] = s_idx[0];
        }
        __syncthreads();

        // ---- gather + max with 64 threads ----
        if (threadIdx.x < CC / 4) {
            const int t = threadIdx.x;
            const float* fb = feat + (size_t)b * NN * CC;
            const float4 a0 = ((const float4*)(fb + (size_t)s_idx[0] * CC))[t];
            const float4 a1 = ((const float4*)(fb + (size_t)s_idx[1] * CC))[t];
            const float4 a2 = ((const float4*)(fb + (size_t)s_idx[2] * CC))[t];
            const float4 a3 = ((const float4*)(fb + (size_t)s_idx[3] * CC))[t];
            float4 r;
            r.x = fmaxf(fmaxf(a0.x, a1.x), fmaxf(a2.x, a3.x));
            r.y = fmaxf(fmaxf(a0.y, a1.y), fmaxf(a2.y, a3.y));
            r.z = fmaxf(fmaxf(a0.z, a1.z), fmaxf(a2.z, a3.z));
            r.w = fmaxf(fmaxf(a0.w, a1.w), fmaxf(a2.w, a3.w));
            ((float4*)(outF + ((size_t)b * POOLN + s) * CC))[t] = r;
        }
        __syncthreads();   // protect s_* reuse across loop iterations
    }

    // ---- self-reset for next replay: last block zeroes the counters ----
    __syncthreads();
    if (threadIdx.x == 0) {
        __threadfence();
        const int done = atomicAdd(&g_hard_done, 1);
        if (done == (int)gridDim.x - 1) {
            g_hard_count = 0;
            g_hard_done  = 0;
            __threadfence();
        }
    }
}

extern "C" void kernel_launch(void* const* d_in, const int* in_sizes, int n_in,
                              void* d_out, int out_size)
{
    const float* verts      = (const float*)d_in[0];
    const float* feat       = (const float*)d_in[1];
    const int*   radius_raw = (const int*)  d_in[2];
    const int*   sample_idx = (const int*)  d_in[3];

    float* outV = (float*)d_out;
    float* outF = (float*)d_out + (size_t)BB * POOLN * 3;

    pool_easy_kernel<<<BB * POOLN / QPB, 256>>>(verts, feat, radius_raw,
                                                sample_idx, outV, outF);
    pool_hard_kernel<<<HARD_GRID, 256>>>(verts, feat, radius_raw, sample_idx, outF);
}